// round 15
// baseline (speedup 1.0000x reference)
#include <cuda_runtime.h>
#include <cuda_bf16.h>
#include <cuda_fp16.h>
#include <cstdint>

// ---------------- problem constants ----------------
#define N_NODES_MAX 50000
#define N_EDGES_MAX 800000
#define N_GRAPHS_MAX 1000
#define HID 128
#define HIDH 64
#define KPAD 128
#define EPS 1e-5f
#define SCAN_B 1024

// ---------------- scratch (device globals, allocation-free) ----------------
__device__ __align__(16) __half g_yh[N_NODES_MAX * HID];    // h @ W_n (fp16)
__device__ __align__(16) __half g_zh[N_NODES_MAX * HID];    // h @ W_r + b + agg (fp16)
__device__ __align__(16) __nv_bfloat16 g_ax_hi[N_NODES_MAX * KPAD];  // layer-0 A split
__device__ __align__(16) __nv_bfloat16 g_ax_lo[N_NODES_MAX * KPAD];
__device__ __align__(16) __nv_bfloat16 g_bw_hi[3][256 * KPAD];   // [Wn|Wr]^T hi, [n][k]
__device__ __align__(16) __nv_bfloat16 g_bw_lo[3][256 * KPAD];
__device__ int   g_is64;
__device__ int   g_indeg[N_NODES_MAX];
__device__ int   g_row_start[N_NODES_MAX + 1];
__device__ int   g_epos[N_NODES_MAX];
__device__ int   g_esrc[N_EDGES_MAX];
__device__ int   g_gstart[N_GRAPHS_MAX + 1];
__device__ float g_statp[3][2 * HID][32];    // padded: one 128B line per stat

// ---------------- index-width handling ----------------
__device__ __forceinline__ int ld_idx(const void* p, long long i, int is64) {
    if (is64) return (int)((const long long*)p)[i];
    return ((const int*)p)[i];
}

// ---------------- combined prep: flag init + zero indeg + zero stats -------
__global__ void prep0_kernel(int N) {
    int i = blockIdx.x * blockDim.x + threadIdx.x;
    if (i == 0) g_is64 = 1;
    if (i < N) g_indeg[i] = 0;
    if (i < 3 * 2 * HID) g_statp[i / (2 * HID)][i % (2 * HID)][0] = 0.f;
}

__global__ void detect_kernel(const void* ei, int n_i32) {
    int i = blockIdx.x * blockDim.x + threadIdx.x;
    int idx = 2 * i + 1;
    if (idx < n_i32 && ((const int*)ei)[idx] != 0) g_is64 = 0;
}

// ---------------- CSR build ----------------
__global__ void count_edges_kernel(const void* __restrict__ ei, int E) {
    int e = blockIdx.x * blockDim.x + threadIdx.x;
    if (e >= E) return;
    atomicAdd(&g_indeg[ld_idx(ei, (long long)E + e, g_is64)], 1);
}

// single-block scan over indeg: row_start/epos exclusive prefix sums.
__global__ void scan_all_kernel(int N, int E) {
    __shared__ int sh[SCAN_B];
    int t = threadIdx.x;
    int chunk = (N + SCAN_B - 1) / SCAN_B;
    int beg = t * chunk;
    int end = beg + chunk;
    if (end > N) end = N;
    int sum = 0;
    for (int i = beg; i < end; i++) sum += g_indeg[i];
    sh[t] = sum;
    __syncthreads();
    #pragma unroll
    for (int off = 1; off < SCAN_B; off <<= 1) {
        int v = 0;
        if (t >= off) v = sh[t - off];
        __syncthreads();
        sh[t] += v;
        __syncthreads();
    }
    int run = sh[t] - sum;   // exclusive prefix of this chunk
    for (int i = beg; i < end; i++) {
        g_row_start[i] = run;
        g_epos[i] = run;
        run += g_indeg[i];
    }
    if (t == 0) g_row_start[N] = E;
}

__global__ void fill_edges_kernel(const void* __restrict__ ei, int E) {
    int e = blockIdx.x * blockDim.x + threadIdx.x;
    if (e >= E) return;
    int is64 = g_is64;
    int s = ld_idx(ei, e, is64);
    int d = ld_idx(ei, (long long)E + e, is64);
    g_esrc[atomicAdd(&g_epos[d], 1)] = s;
}

__global__ void gstart_kernel(const void* __restrict__ batch, int N, int G) {
    int i = blockIdx.x * blockDim.x + threadIdx.x;
    if (i > N) return;
    int is64 = g_is64;
    int cur  = (i == N) ? G : ld_idx(batch, i, is64);
    int prev = (i == 0) ? -1 : ld_idx(batch, i - 1, is64);
    for (int g = prev + 1; g <= cur && g <= G; g++) g_gstart[g] = i;
}

// ---------------- bf16 split conversions ----------------
// writes only the first KW columns (row stride stays KPAD)
__global__ void convert_x_kernel(const float* __restrict__ x, int N, int IN_CH, int KW) {
    int idx = blockIdx.x * blockDim.x + threadIdx.x;
    if (idx >= N * KW) return;
    int r = idx / KW, k = idx % KW;
    float v = (k < IN_CH) ? x[(size_t)r * IN_CH + k] : 0.f;
    __nv_bfloat16 hi = __float2bfloat16(v);
    size_t o = (size_t)r * KPAD + k;
    g_ax_hi[o] = hi;
    g_ax_lo[o] = __float2bfloat16(v - __bfloat162float(hi));
}

// one launch for all 3 layers: blockIdx.y = layer
__global__ void prep_weights_kernel(const float* __restrict__ Wn0, const float* __restrict__ Wr0,
                                    const float* __restrict__ Wn1, const float* __restrict__ Wr1,
                                    const float* __restrict__ Wn2, const float* __restrict__ Wr2,
                                    int IN_CH) {
    int idx = blockIdx.x * blockDim.x + threadIdx.x;
    if (idx >= 256 * KPAD) return;
    int layer = blockIdx.y;
    const float* Wn = (layer == 0) ? Wn0 : (layer == 1) ? Wn1 : Wn2;
    const float* Wr = (layer == 0) ? Wr0 : (layer == 1) ? Wr1 : Wr2;
    int K_real = (layer == 0) ? IN_CH : HID;
    int n = idx >> 7, k = idx & 127;
    float v = 0.f;
    if (k < K_real) v = (n < HID) ? Wn[(size_t)k * HID + n] : Wr[(size_t)k * HID + (n - HID)];
    __nv_bfloat16 hi = __float2bfloat16(v);
    g_bw_hi[layer][idx] = hi;
    g_bw_lo[layer][idx] = __float2bfloat16(v - __bfloat162float(hi));
}

// ---------------- mma.sync dual GEMM (split halves, 3-tile SMEM) -----------
// Template: KSTEPS = k16 steps (5 for layer 0, 8 for layers 1/2);
//           NORM   = A comes from g_zh with fused BN+ReLU+bf16-split
// grid (nb, 2). blockIdx.y: 0 -> g_yh (fp16), 1 -> g_zh (fp16 + bias).
// Phase 1: A_hi x (B_hi, B_lo); [reload A with A_lo]; Phase 2: A_lo x B_hi.
#define PITCH 272
#define A_TILE (128 * PITCH)            // 34816
#define SM_A    0
#define SM_B_HI A_TILE
#define SM_B_LO (2 * A_TILE)
#define SM_TOTAL (3 * A_TILE)           // 104448

__device__ __forceinline__ uint32_t smem_u32(const void* p) {
    uint32_t a;
    asm("{ .reg .u64 t; cvta.to.shared.u64 t, %1; cvt.u32.u64 %0, t; }" : "=r"(a) : "l"(p));
    return a;
}

__device__ __forceinline__ void ldsm_x4(uint32_t& r0, uint32_t& r1, uint32_t& r2, uint32_t& r3,
                                        uint32_t addr) {
    asm volatile("ldmatrix.sync.aligned.m8n8.x4.shared.b16 {%0,%1,%2,%3}, [%4];"
                 : "=r"(r0), "=r"(r1), "=r"(r2), "=r"(r3) : "r"(addr));
}

__device__ __forceinline__ void mma16816(float* c, const uint32_t* a, const uint32_t* b) {
    asm volatile(
        "mma.sync.aligned.m16n8k16.row.col.f32.bf16.bf16.f32 "
        "{%0,%1,%2,%3}, {%4,%5,%6,%7}, {%8,%9}, {%0,%1,%2,%3};"
        : "+f"(c[0]), "+f"(c[1]), "+f"(c[2]), "+f"(c[3])
        : "r"(a[0]), "r"(a[1]), "r"(a[2]), "r"(a[3]), "r"(b[0]), "r"(b[1]));
}

// convert one 8-element chunk of z-row into normed/relu'd fp32
__device__ __forceinline__ void z_to_h8(const __half* zrow, const float* s_sc,
                                        const float* s_sh, int cbase, float* h) {
    uint4 vz = *(const uint4*)zrow;
    const __half2* hp = (const __half2*)&vz;
    #pragma unroll
    for (int j = 0; j < 4; j++) {
        float2 f = __half22float2(hp[j]);
        h[2 * j]     = f.x;
        h[2 * j + 1] = f.y;
    }
    #pragma unroll
    for (int j = 0; j < 8; j++)
        h[j] = fmaxf(fmaf(h[j], s_sc[cbase + j], s_sh[cbase + j]), 0.f);
}

template <int KSTEPS, bool NORM>
__global__ __launch_bounds__(256, 2)
void gemm_mma_kernel(const uint4* __restrict__ a_hi, const uint4* __restrict__ a_lo,
                     const uint4* __restrict__ b_hi, const uint4* __restrict__ b_lo,
                     const float* __restrict__ bias,
                     const float* __restrict__ pgamma, const float* __restrict__ pbeta,
                     int prev_layer, int M)
{
    constexpr int CR = 2 * KSTEPS;      // uint4 column-chunks used per row
    extern __shared__ char smem[];
    __shared__ float s_sc[HID];
    __shared__ float s_sh[HID];
    uint32_t sbase = smem_u32(smem);

    int tid = threadIdx.x;
    int lane = tid & 31;
    int wid = tid >> 5;
    int wm = wid & 3;
    int wn = wid >> 2;
    int row0 = blockIdx.x * 128;
    int half = blockIdx.y;
    int brow0 = half * 128;

    if (NORM) {
        if (tid < HID) {
            float inv_m = 1.0f / (float)M;
            float mu = g_statp[prev_layer][tid][0] * inv_m;
            float var = fmaxf(g_statp[prev_layer][HID + tid][0] * inv_m - mu * mu, 0.f);
            float sc = pgamma[tid] * rsqrtf(var + EPS);
            s_sc[tid] = sc;
            s_sh[tid] = pbeta[tid] - mu * sc;
        }
        __syncthreads();
    }

    // ---- load A_hi + both B tiles ----
    #pragma unroll
    for (int i = tid; i < 128 * CR; i += 256) {
        int r = i / CR, c16 = i % CR;
        int doff = r * PITCH + c16 * 16;
        uint4 vh = make_uint4(0, 0, 0, 0);
        if (row0 + r < M) {
            if (NORM) {
                float h[8];
                z_to_h8(g_zh + (size_t)(row0 + r) * HID + c16 * 8, s_sc, s_sh, c16 * 8, h);
                __nv_bfloat162* o = (__nv_bfloat162*)&vh;
                #pragma unroll
                for (int j = 0; j < 4; j++)
                    o[j] = __nv_bfloat162(__float2bfloat16(h[2 * j]),
                                          __float2bfloat16(h[2 * j + 1]));
            } else {
                vh = a_hi[(size_t)(row0 + r) * 16 + c16];
            }
        }
        *(uint4*)(smem + SM_A + doff) = vh;
        *(uint4*)(smem + SM_B_HI + doff) = b_hi[(size_t)(brow0 + r) * 16 + c16];
        *(uint4*)(smem + SM_B_LO + doff) = b_lo[(size_t)(brow0 + r) * 16 + c16];
    }
    __syncthreads();

    float acc[2][8][4];
    #pragma unroll
    for (int mi = 0; mi < 2; mi++)
        #pragma unroll
        for (int ni = 0; ni < 8; ni++)
            #pragma unroll
            for (int q = 0; q < 4; q++) acc[mi][ni][q] = 0.f;

    uint32_t a_off[2];
    #pragma unroll
    for (int mi = 0; mi < 2; mi++)
        a_off[mi] = (uint32_t)((wm * 32 + mi * 16 + (lane & 15)) * PITCH + (lane >> 4) * 16);
    uint32_t b_off[4];
    {
        int grp = lane >> 3, rin = lane & 7;
        int radd = (grp >= 2) ? 8 : 0;
        int koff = (grp & 1) * 16;
        #pragma unroll
        for (int pi = 0; pi < 4; pi++)
            b_off[pi] = (uint32_t)((wn * 64 + pi * 16 + radd + rin) * PITCH + koff);
    }

    uint32_t smA  = sbase + SM_A;
    uint32_t smBH = sbase + SM_B_HI;
    uint32_t smBL = sbase + SM_B_LO;

    // ---- phase 1: A_hi x B_hi and A_hi x B_lo (shared A fragments) ----
    #pragma unroll
    for (int k16 = 0; k16 < KSTEPS; k16++) {
        uint32_t kadd = k16 * 32;
        uint32_t afr[2][4];
        #pragma unroll
        for (int mi = 0; mi < 2; mi++)
            ldsm_x4(afr[mi][0], afr[mi][1], afr[mi][2], afr[mi][3],
                    smA + a_off[mi] + kadd);
        uint32_t bfr[8][2];
        #pragma unroll
        for (int pi = 0; pi < 4; pi++) {
            uint32_t r0, r1, r2, r3;
            ldsm_x4(r0, r1, r2, r3, smBH + b_off[pi] + kadd);
            bfr[pi * 2][0] = r0; bfr[pi * 2][1] = r1;
            bfr[pi * 2 + 1][0] = r2; bfr[pi * 2 + 1][1] = r3;
        }
        #pragma unroll
        for (int ni = 0; ni < 8; ni++) {
            mma16816(acc[0][ni], afr[0], bfr[ni]);
            mma16816(acc[1][ni], afr[1], bfr[ni]);
        }
        #pragma unroll
        for (int pi = 0; pi < 4; pi++) {
            uint32_t r0, r1, r2, r3;
            ldsm_x4(r0, r1, r2, r3, smBL + b_off[pi] + kadd);
            bfr[pi * 2][0] = r0; bfr[pi * 2][1] = r1;
            bfr[pi * 2 + 1][0] = r2; bfr[pi * 2 + 1][1] = r3;
        }
        #pragma unroll
        for (int ni = 0; ni < 8; ni++) {
            mma16816(acc[0][ni], afr[0], bfr[ni]);
            mma16816(acc[1][ni], afr[1], bfr[ni]);
        }
    }

    // ---- reload A tile with A_lo ----
    __syncthreads();
    #pragma unroll
    for (int i = tid; i < 128 * CR; i += 256) {
        int r = i / CR, c16 = i % CR;
        int doff = r * PITCH + c16 * 16;
        uint4 vl = make_uint4(0, 0, 0, 0);
        if (row0 + r < M) {
            if (NORM) {
                float h[8];
                z_to_h8(g_zh + (size_t)(row0 + r) * HID + c16 * 8, s_sc, s_sh, c16 * 8, h);
                __nv_bfloat162* o = (__nv_bfloat162*)&vl;
                #pragma unroll
                for (int j = 0; j < 4; j++) {
                    float h0 = h[2 * j], h1 = h[2 * j + 1];
                    __nv_bfloat16 hi0 = __float2bfloat16(h0);
                    __nv_bfloat16 hi1 = __float2bfloat16(h1);
                    o[j] = __nv_bfloat162(__float2bfloat16(h0 - __bfloat162float(hi0)),
                                          __float2bfloat16(h1 - __bfloat162float(hi1)));
                }
            } else {
                vl = a_lo[(size_t)(row0 + r) * 16 + c16];
            }
        }
        *(uint4*)(smem + SM_A + doff) = vl;
    }
    __syncthreads();

    // ---- phase 2: A_lo x B_hi ----
    #pragma unroll
    for (int k16 = 0; k16 < KSTEPS; k16++) {
        uint32_t kadd = k16 * 32;
        uint32_t afr[2][4];
        #pragma unroll
        for (int mi = 0; mi < 2; mi++)
            ldsm_x4(afr[mi][0], afr[mi][1], afr[mi][2], afr[mi][3],
                    smA + a_off[mi] + kadd);
        uint32_t bfr[8][2];
        #pragma unroll
        for (int pi = 0; pi < 4; pi++) {
            uint32_t r0, r1, r2, r3;
            ldsm_x4(r0, r1, r2, r3, smBH + b_off[pi] + kadd);
            bfr[pi * 2][0] = r0; bfr[pi * 2][1] = r1;
            bfr[pi * 2 + 1][0] = r2; bfr[pi * 2 + 1][1] = r3;
        }
        #pragma unroll
        for (int ni = 0; ni < 8; ni++) {
            mma16816(acc[0][ni], afr[0], bfr[ni]);
            mma16816(acc[1][ni], afr[1], bfr[ni]);
        }
    }

    // ---- epilogue: half 0 -> g_yh (fp16), half 1 -> g_zh (fp16 + bias) ----
    __half* O = half ? g_zh : g_yh;
    #pragma unroll
    for (int mi = 0; mi < 2; mi++) {
        int r0 = row0 + wm * 32 + mi * 16 + (lane >> 2);
        #pragma unroll
        for (int ni = 0; ni < 8; ni++) {
            int c = wn * 64 + ni * 8 + (lane & 3) * 2;
            float bx = 0.f, by = 0.f;
            if (half) { bx = bias[c]; by = bias[c + 1]; }
            if (r0 < M) {
                __half2 v = __floats2half2_rn(acc[mi][ni][0] + bx, acc[mi][ni][1] + by);
                *(__half2*)&O[(size_t)r0 * HID + c] = v;
            }
            if (r0 + 8 < M) {
                __half2 v = __floats2half2_rn(acc[mi][ni][2] + bx, acc[mi][ni][3] + by);
                *(__half2*)&O[(size_t)(r0 + 8) * HID + c] = v;
            }
        }
    }
}

// ---------------- gather-mean + fused BN stats ------------------------------
__global__ void aggregate_kernel(int N, int layer) {
    __shared__ float sh_s[8][132];
    __shared__ float sh_q[8][132];
    int wid = threadIdx.x >> 5;
    int lane = threadIdx.x & 31;
    int d = blockIdx.x * 8 + wid;

    float4 z = make_float4(0.f, 0.f, 0.f, 0.f);
    if (d < N) {
        int s0 = g_row_start[d];
        int s1 = g_row_start[d + 1];
        int deg = s1 - s0;
        float inv = 1.0f / (float)(deg > 1 ? deg : 1);
        const uint2* Y = (const uint2*)g_yh;

        float4 acc = make_float4(0.f, 0.f, 0.f, 0.f);
        int j = s0;
        // 8-wide unroll: 8 outstanding 8B loads per lane
        for (; j + 7 < s1; j += 8) {
            uint2 u[8];
            #pragma unroll
            for (int q = 0; q < 8; q++)
                u[q] = Y[(size_t)g_esrc[j + q] * 32 + lane];
            #pragma unroll
            for (int q = 0; q < 8; q++) {
                float2 f0 = __half22float2(*(__half2*)&u[q].x);
                float2 f1 = __half22float2(*(__half2*)&u[q].y);
                acc.x += f0.x; acc.y += f0.y; acc.z += f1.x; acc.w += f1.y;
            }
        }
        for (; j + 3 < s1; j += 4) {
            uint2 u[4];
            #pragma unroll
            for (int q = 0; q < 4; q++)
                u[q] = Y[(size_t)g_esrc[j + q] * 32 + lane];
            #pragma unroll
            for (int q = 0; q < 4; q++) {
                float2 f0 = __half22float2(*(__half2*)&u[q].x);
                float2 f1 = __half22float2(*(__half2*)&u[q].y);
                acc.x += f0.x; acc.y += f0.y; acc.z += f1.x; acc.w += f1.y;
            }
        }
        for (; j < s1; j++) {
            uint2 ua = Y[(size_t)g_esrc[j] * 32 + lane];
            float2 a0 = __half22float2(*(__half2*)&ua.x), a1 = __half22float2(*(__half2*)&ua.y);
            acc.x += a0.x; acc.y += a0.y; acc.z += a1.x; acc.w += a1.y;
        }

        uint2 uz = ((const uint2*)g_zh)[(size_t)d * 32 + lane];
        float2 z01 = __half22float2(*(__half2*)&uz.x);
        float2 z23 = __half22float2(*(__half2*)&uz.y);
        z.x = fmaf(acc.x, inv, z01.x);
        z.y = fmaf(acc.y, inv, z01.y);
        z.z = fmaf(acc.z, inv, z23.x);
        z.w = fmaf(acc.w, inv, z23.y);
        uint2 uo;
        *(__half2*)&uo.x = __floats2half2_rn(z.x, z.y);
        *(__half2*)&uo.y = __floats2half2_rn(z.z, z.w);
        ((uint2*)g_zh)[(size_t)d * 32 + lane] = uo;
    }

    // fused BN stats
    float4 q = make_float4(z.x * z.x, z.y * z.y, z.z * z.z, z.w * z.w);
    *(float4*)&sh_s[wid][4 * lane] = z;
    *(float4*)&sh_q[wid][4 * lane] = q;
    __syncthreads();
    int t = threadIdx.x;
    if (t < HID) {
        float s = 0.f;
        #pragma unroll
        for (int w = 0; w < 8; w++) s += sh_s[w][t];
        atomicAdd(&g_statp[layer][t][0], s);
    } else {
        int c = t - HID;
        float s = 0.f;
        #pragma unroll
        for (int w = 0; w < 8; w++) s += sh_q[w][c];
        atomicAdd(&g_statp[layer][HID + c][0], s);
    }
}

// ---------------- fused norm + global mean pool + MLP head ------------------
__global__ void pool_head_kernel(const float* __restrict__ gamma,
                                 const float* __restrict__ beta,
                                 const float* __restrict__ Wh1,
                                 const float* __restrict__ bh1,
                                 const float* __restrict__ Wh2,
                                 const float* __restrict__ bh2,
                                 float* __restrict__ out, int G, int N)
{
    __shared__ float s_sc[HID];
    __shared__ float s_sh[HID];
    __shared__ float pooled[HID];
    __shared__ float sred[2];
    int g = blockIdx.x;
    int t = threadIdx.x;   // 0..127
    if (g >= G) return;

    if (t < HID) {
        float inv_m = 1.0f / (float)N;
        float mu = g_statp[2][t][0] * inv_m;
        float var = fmaxf(g_statp[2][HID + t][0] * inv_m - mu * mu, 0.f);
        float sc = gamma[t] * rsqrtf(var + EPS);
        s_sc[t] = sc;
        s_sh[t] = beta[t] - mu * sc;
    }
    __syncthreads();

    int r0 = g_gstart[g];
    int r1 = g_gstart[g + 1];
    float sc = s_sc[t], sh = s_sh[t];
    float s = 0.f;
    for (int r = r0; r < r1; r++) {
        float z = __half2float(g_zh[(size_t)r * HID + t]);
        s += fmaxf(fmaf(z, sc, sh), 0.f);
    }
    int cnt = r1 - r0;
    pooled[t] = s / (float)(cnt > 1 ? cnt : 1);
    __syncthreads();

    if (t < HIDH) {
        float acc = bh1[t];
        #pragma unroll 8
        for (int k = 0; k < HID; k++)
            acc = fmaf(pooled[k], Wh1[k * HIDH + t], acc);
        float v = fmaxf(acc, 0.f) * Wh2[t];
        #pragma unroll
        for (int off = 16; off; off >>= 1)
            v += __shfl_down_sync(0xffffffff, v, off);
        if ((t & 31) == 0) sred[t >> 5] = v;
    }
    __syncthreads();
    if (t == 0) out[g] = sred[0] + sred[1] + bh2[0];
}

// ---------------- launch ----------------
extern "C" void kernel_launch(void* const* d_in, const int* in_sizes, int n_in,
                              void* d_out, int out_size) {
    const float* x     = (const float*)d_in[0];
    const void*  ei    = d_in[1];
    const void*  batch = d_in[2];

    const float* W_n0 = (const float*)d_in[3];
    const float* b0   = (const float*)d_in[4];
    const float* W_r0 = (const float*)d_in[5];
    const float* g0   = (const float*)d_in[6];
    const float* be0  = (const float*)d_in[7];

    const float* W_n1 = (const float*)d_in[8];
    const float* b1   = (const float*)d_in[9];
    const float* W_r1 = (const float*)d_in[10];
    const float* g1   = (const float*)d_in[11];
    const float* be1  = (const float*)d_in[12];

    const float* W_n2 = (const float*)d_in[13];
    const float* b2   = (const float*)d_in[14];
    const float* W_r2 = (const float*)d_in[15];
    const float* g2   = (const float*)d_in[16];
    const float* be2  = (const float*)d_in[17];

    const float* Wh1 = (const float*)d_in[18];
    const float* bh1 = (const float*)d_in[19];
    const float* Wh2 = (const float*)d_in[20];
    const float* bh2 = (const float*)d_in[21];

    float* out = (float*)d_out;

    const int N = in_sizes[2];
    const int E = in_sizes[1] / 2;
    const int G = out_size;
    const int IN_CH = in_sizes[0] / N;

    cudaFuncSetAttribute((const void*)gemm_mma_kernel<5, false>,
                         cudaFuncAttributeMaxDynamicSharedMemorySize, SM_TOTAL);
    cudaFuncSetAttribute((const void*)gemm_mma_kernel<8, false>,
                         cudaFuncAttributeMaxDynamicSharedMemorySize, SM_TOTAL);
    cudaFuncSetAttribute((const void*)gemm_mma_kernel<8, true>,
                         cudaFuncAttributeMaxDynamicSharedMemorySize, SM_TOTAL);

    // ---- prep: flag/zero, detect dtype, CSR, segments ----
    prep0_kernel<<<(N + 255) / 256, 256>>>(N);
    detect_kernel<<<8, 256>>>(ei, in_sizes[1]);
    count_edges_kernel<<<(E + 255) / 256, 256>>>(ei, E);
    scan_all_kernel<<<1, SCAN_B>>>(N, E);
    fill_edges_kernel<<<(E + 255) / 256, 256>>>(ei, E);
    gstart_kernel<<<(N + 256) / 256, 256>>>(batch, N, G);

    // ---- bf16 split preprocessing ----
    int ksteps0 = (IN_CH + 15) / 16;   // 5 for IN_CH=78
    int KW = (ksteps0 <= 5) ? 80 : KPAD;
    convert_x_kernel<<<(N * KW + 255) / 256, 256>>>(x, N, IN_CH, KW);
    {
        dim3 wgrid((256 * KPAD + 255) / 256, 3);
        prep_weights_kernel<<<wgrid, 256>>>(W_n0, W_r0, W_n1, W_r1, W_n2, W_r2, IN_CH);
    }

    dim3 gemm_grid((N + 127) / 128, 2);
    int agg_blocks = (N + 7) / 8;

    const float* bb[3] = {b0, b1, b2};
    const float* gg[3] = {g0, g1, g2};
    const float* be[3] = {be0, be1, be2};

    for (int l = 0; l < 3; l++) {
        const uint4* ahi = nullptr;
        const uint4* alo = nullptr;
        const uint4* bhi;
        const uint4* blo;
        void* p;
        if (l == 0) {
            cudaGetSymbolAddress(&p, g_ax_hi); ahi = (const uint4*)p;
            cudaGetSymbolAddress(&p, g_ax_lo); alo = (const uint4*)p;
        }
        cudaGetSymbolAddress(&p, g_bw_hi); bhi = (const uint4*)p + (size_t)l * (256 * KPAD / 8);
        cudaGetSymbolAddress(&p, g_bw_lo); blo = (const uint4*)p + (size_t)l * (256 * KPAD / 8);

        if (l == 0) {
            if (ksteps0 <= 5)
                gemm_mma_kernel<5, false><<<gemm_grid, 256, SM_TOTAL>>>(
                    ahi, alo, bhi, blo, bb[l], nullptr, nullptr, 0, N);
            else
                gemm_mma_kernel<8, false><<<gemm_grid, 256, SM_TOTAL>>>(
                    ahi, alo, bhi, blo, bb[l], nullptr, nullptr, 0, N);
        } else {
            gemm_mma_kernel<8, true><<<gemm_grid, 256, SM_TOTAL>>>(
                nullptr, nullptr, bhi, blo, bb[l], gg[l - 1], be[l - 1], l - 1, N);
        }
        aggregate_kernel<<<agg_blocks, 256>>>(N, l);
    }

    pool_head_kernel<<<G, HID>>>(gg[2], be[2], Wh1, bh1, Wh2, bh2, out, G, N);
}

// round 16
// speedup vs baseline: 1.1958x; 1.1958x over previous
#include <cuda_runtime.h>
#include <cuda_bf16.h>
#include <cuda_fp16.h>
#include <cstdint>

// ---------------- problem constants ----------------
#define N_NODES_MAX 50000
#define N_EDGES_MAX 800000
#define N_GRAPHS_MAX 1000
#define HID 128
#define HIDH 64
#define KPAD 128
#define EPS 1e-5f
#define SCAN_B 1024
#define MAX_BLOCKS ((N_NODES_MAX + SCAN_B - 1) / SCAN_B)

// ---------------- scratch (device globals, allocation-free) ----------------
__device__ __align__(16) __half g_yh[N_NODES_MAX * HID];    // h @ W_n (fp16)
__device__ __align__(16) __half g_zh[N_NODES_MAX * HID];    // h @ W_r + b + agg (fp16)
__device__ __align__(16) __nv_bfloat16 g_ax_hi[N_NODES_MAX * KPAD];  // layer-0 A split
__device__ __align__(16) __nv_bfloat16 g_ax_lo[N_NODES_MAX * KPAD];
__device__ __align__(16) __nv_bfloat16 g_bw_hi[3][256 * KPAD];   // [Wn|Wr]^T hi, [n][k]
__device__ __align__(16) __nv_bfloat16 g_bw_lo[3][256 * KPAD];
__device__ int   g_is64;
__device__ int   g_indeg[N_NODES_MAX];
__device__ int   g_rowexcl[N_NODES_MAX];
__device__ int   g_bsum[MAX_BLOCKS];
__device__ int   g_bsumex[MAX_BLOCKS];
__device__ int   g_row_start[N_NODES_MAX + 1];
__device__ int   g_epos[N_NODES_MAX];
__device__ int   g_esrc[N_EDGES_MAX];
__device__ int   g_gstart[N_GRAPHS_MAX + 1];
__device__ float g_statp[3][2 * HID][32];    // padded: one 128B line per stat

// ---------------- index-width handling ----------------
__device__ __forceinline__ int ld_idx(const void* p, long long i, int is64) {
    if (is64) return (int)((const long long*)p)[i];
    return ((const int*)p)[i];
}

// ---------------- combined prep: flag init + zero indeg + zero stats -------
__global__ void prep0_kernel(int N) {
    int i = blockIdx.x * blockDim.x + threadIdx.x;
    if (i == 0) g_is64 = 1;
    if (i < N) g_indeg[i] = 0;
    if (i < 3 * 2 * HID) g_statp[i / (2 * HID)][i % (2 * HID)][0] = 0.f;
}

__global__ void detect_kernel(const void* ei, int n_i32) {
    int i = blockIdx.x * blockDim.x + threadIdx.x;
    int idx = 2 * i + 1;
    if (idx < n_i32 && ((const int*)ei)[idx] != 0) g_is64 = 0;
}

// ---------------- CSR build ----------------
__global__ void count_edges_kernel(const void* __restrict__ ei, int E) {
    int e = blockIdx.x * blockDim.x + threadIdx.x;
    if (e >= E) return;
    atomicAdd(&g_indeg[ld_idx(ei, (long long)E + e, g_is64)], 1);
}

__global__ void scan1_kernel(int N) {
    __shared__ int sh[SCAN_B];
    int i = blockIdx.x * SCAN_B + threadIdx.x;
    int v = (i < N) ? g_indeg[i] : 0;
    sh[threadIdx.x] = v;
    __syncthreads();
    #pragma unroll
    for (int off = 1; off < SCAN_B; off <<= 1) {
        int t = 0;
        if (threadIdx.x >= off) t = sh[threadIdx.x - off];
        __syncthreads();
        sh[threadIdx.x] += t;
        __syncthreads();
    }
    if (i < N) g_rowexcl[i] = sh[threadIdx.x] - v;
    if (threadIdx.x == SCAN_B - 1) g_bsum[blockIdx.x] = sh[SCAN_B - 1];
}

__global__ void scan2_kernel(int nblocks) {
    if (threadIdx.x == 0) {
        int run = 0;
        for (int b = 0; b < nblocks; b++) { int t = g_bsum[b]; g_bsumex[b] = run; run += t; }
    }
}

__global__ void scan3_kernel(int N, int E) {
    int i = blockIdx.x * blockDim.x + threadIdx.x;
    if (i < N) {
        int v = g_rowexcl[i] + g_bsumex[i >> 10];
        g_row_start[i] = v;
        g_epos[i] = v;
    }
    if (i == 0) g_row_start[N] = E;
}

__global__ void fill_edges_kernel(const void* __restrict__ ei, int E) {
    int e = blockIdx.x * blockDim.x + threadIdx.x;
    if (e >= E) return;
    int is64 = g_is64;
    int s = ld_idx(ei, e, is64);
    int d = ld_idx(ei, (long long)E + e, is64);
    g_esrc[atomicAdd(&g_epos[d], 1)] = s;
}

__global__ void gstart_kernel(const void* __restrict__ batch, int N, int G) {
    int i = blockIdx.x * blockDim.x + threadIdx.x;
    if (i > N) return;
    int is64 = g_is64;
    int cur  = (i == N) ? G : ld_idx(batch, i, is64);
    int prev = (i == 0) ? -1 : ld_idx(batch, i - 1, is64);
    for (int g = prev + 1; g <= cur && g <= G; g++) g_gstart[g] = i;
}

// ---------------- bf16 split conversions ----------------
// writes only the first KW columns (row stride stays KPAD)
__global__ void convert_x_kernel(const float* __restrict__ x, int N, int IN_CH, int KW) {
    int idx = blockIdx.x * blockDim.x + threadIdx.x;
    if (idx >= N * KW) return;
    int r = idx / KW, k = idx % KW;
    float v = (k < IN_CH) ? x[(size_t)r * IN_CH + k] : 0.f;
    __nv_bfloat16 hi = __float2bfloat16(v);
    size_t o = (size_t)r * KPAD + k;
    g_ax_hi[o] = hi;
    g_ax_lo[o] = __float2bfloat16(v - __bfloat162float(hi));
}

// one launch for all 3 layers: blockIdx.y = layer
__global__ void prep_weights_kernel(const float* __restrict__ Wn0, const float* __restrict__ Wr0,
                                    const float* __restrict__ Wn1, const float* __restrict__ Wr1,
                                    const float* __restrict__ Wn2, const float* __restrict__ Wr2,
                                    int IN_CH) {
    int idx = blockIdx.x * blockDim.x + threadIdx.x;
    if (idx >= 256 * KPAD) return;
    int layer = blockIdx.y;
    const float* Wn = (layer == 0) ? Wn0 : (layer == 1) ? Wn1 : Wn2;
    const float* Wr = (layer == 0) ? Wr0 : (layer == 1) ? Wr1 : Wr2;
    int K_real = (layer == 0) ? IN_CH : HID;
    int n = idx >> 7, k = idx & 127;
    float v = 0.f;
    if (k < K_real) v = (n < HID) ? Wn[(size_t)k * HID + n] : Wr[(size_t)k * HID + (n - HID)];
    __nv_bfloat16 hi = __float2bfloat16(v);
    g_bw_hi[layer][idx] = hi;
    g_bw_lo[layer][idx] = __float2bfloat16(v - __bfloat162float(hi));
}

// ---------------- mma.sync dual GEMM (split halves, 3-tile SMEM) -----------
// Template: KSTEPS = k16 steps (5 for layer 0, 8 for layers 1/2);
//           NORM   = A comes from g_zh with fused BN+ReLU+bf16-split
// grid (nb, 2). blockIdx.y: 0 -> g_yh (fp16), 1 -> g_zh (fp16 + bias).
// Phase 1: A_hi x (B_hi, B_lo); [reload A with A_lo]; Phase 2: A_lo x B_hi.
#define PITCH 272
#define A_TILE (128 * PITCH)            // 34816
#define SM_A    0
#define SM_B_HI A_TILE
#define SM_B_LO (2 * A_TILE)
#define SM_TOTAL (3 * A_TILE)           // 104448

__device__ __forceinline__ uint32_t smem_u32(const void* p) {
    uint32_t a;
    asm("{ .reg .u64 t; cvta.to.shared.u64 t, %1; cvt.u32.u64 %0, t; }" : "=r"(a) : "l"(p));
    return a;
}

__device__ __forceinline__ void ldsm_x4(uint32_t& r0, uint32_t& r1, uint32_t& r2, uint32_t& r3,
                                        uint32_t addr) {
    asm volatile("ldmatrix.sync.aligned.m8n8.x4.shared.b16 {%0,%1,%2,%3}, [%4];"
                 : "=r"(r0), "=r"(r1), "=r"(r2), "=r"(r3) : "r"(addr));
}

__device__ __forceinline__ void mma16816(float* c, const uint32_t* a, const uint32_t* b) {
    asm volatile(
        "mma.sync.aligned.m16n8k16.row.col.f32.bf16.bf16.f32 "
        "{%0,%1,%2,%3}, {%4,%5,%6,%7}, {%8,%9}, {%0,%1,%2,%3};"
        : "+f"(c[0]), "+f"(c[1]), "+f"(c[2]), "+f"(c[3])
        : "r"(a[0]), "r"(a[1]), "r"(a[2]), "r"(a[3]), "r"(b[0]), "r"(b[1]));
}

// convert one 8-element chunk of z-row into normed/relu'd fp32
__device__ __forceinline__ void z_to_h8(const __half* zrow, const float* s_sc,
                                        const float* s_sh, int cbase, float* h) {
    uint4 vz = *(const uint4*)zrow;
    const __half2* hp = (const __half2*)&vz;
    #pragma unroll
    for (int j = 0; j < 4; j++) {
        float2 f = __half22float2(hp[j]);
        h[2 * j]     = f.x;
        h[2 * j + 1] = f.y;
    }
    #pragma unroll
    for (int j = 0; j < 8; j++)
        h[j] = fmaxf(fmaf(h[j], s_sc[cbase + j], s_sh[cbase + j]), 0.f);
}

template <int KSTEPS, bool NORM>
__global__ __launch_bounds__(256, 2)
void gemm_mma_kernel(const uint4* __restrict__ a_hi, const uint4* __restrict__ a_lo,
                     const uint4* __restrict__ b_hi, const uint4* __restrict__ b_lo,
                     const float* __restrict__ bias,
                     const float* __restrict__ pgamma, const float* __restrict__ pbeta,
                     int prev_layer, int M)
{
    constexpr int CR = 2 * KSTEPS;      // uint4 column-chunks used per row
    extern __shared__ char smem[];
    __shared__ float s_sc[HID];
    __shared__ float s_sh[HID];
    uint32_t sbase = smem_u32(smem);

    int tid = threadIdx.x;
    int lane = tid & 31;
    int wid = tid >> 5;
    int wm = wid & 3;
    int wn = wid >> 2;
    int row0 = blockIdx.x * 128;
    int half = blockIdx.y;
    int brow0 = half * 128;

    if (NORM) {
        if (tid < HID) {
            float inv_m = 1.0f / (float)M;
            float mu = g_statp[prev_layer][tid][0] * inv_m;
            float var = fmaxf(g_statp[prev_layer][HID + tid][0] * inv_m - mu * mu, 0.f);
            float sc = pgamma[tid] * rsqrtf(var + EPS);
            s_sc[tid] = sc;
            s_sh[tid] = pbeta[tid] - mu * sc;
        }
        __syncthreads();
    }

    // ---- load A_hi + both B tiles ----
    #pragma unroll
    for (int i = tid; i < 128 * CR; i += 256) {
        int r = i / CR, c16 = i % CR;
        int doff = r * PITCH + c16 * 16;
        uint4 vh = make_uint4(0, 0, 0, 0);
        if (row0 + r < M) {
            if (NORM) {
                float h[8];
                z_to_h8(g_zh + (size_t)(row0 + r) * HID + c16 * 8, s_sc, s_sh, c16 * 8, h);
                __nv_bfloat162* o = (__nv_bfloat162*)&vh;
                #pragma unroll
                for (int j = 0; j < 4; j++)
                    o[j] = __nv_bfloat162(__float2bfloat16(h[2 * j]),
                                          __float2bfloat16(h[2 * j + 1]));
            } else {
                vh = a_hi[(size_t)(row0 + r) * 16 + c16];
            }
        }
        *(uint4*)(smem + SM_A + doff) = vh;
        *(uint4*)(smem + SM_B_HI + doff) = b_hi[(size_t)(brow0 + r) * 16 + c16];
        *(uint4*)(smem + SM_B_LO + doff) = b_lo[(size_t)(brow0 + r) * 16 + c16];
    }
    __syncthreads();

    float acc[2][8][4];
    #pragma unroll
    for (int mi = 0; mi < 2; mi++)
        #pragma unroll
        for (int ni = 0; ni < 8; ni++)
            #pragma unroll
            for (int q = 0; q < 4; q++) acc[mi][ni][q] = 0.f;

    uint32_t a_off[2];
    #pragma unroll
    for (int mi = 0; mi < 2; mi++)
        a_off[mi] = (uint32_t)((wm * 32 + mi * 16 + (lane & 15)) * PITCH + (lane >> 4) * 16);
    uint32_t b_off[4];
    {
        int grp = lane >> 3, rin = lane & 7;
        int radd = (grp >= 2) ? 8 : 0;
        int koff = (grp & 1) * 16;
        #pragma unroll
        for (int pi = 0; pi < 4; pi++)
            b_off[pi] = (uint32_t)((wn * 64 + pi * 16 + radd + rin) * PITCH + koff);
    }

    uint32_t smA  = sbase + SM_A;
    uint32_t smBH = sbase + SM_B_HI;
    uint32_t smBL = sbase + SM_B_LO;

    // ---- phase 1: A_hi x B_hi and A_hi x B_lo (shared A fragments) ----
    #pragma unroll
    for (int k16 = 0; k16 < KSTEPS; k16++) {
        uint32_t kadd = k16 * 32;
        uint32_t afr[2][4];
        #pragma unroll
        for (int mi = 0; mi < 2; mi++)
            ldsm_x4(afr[mi][0], afr[mi][1], afr[mi][2], afr[mi][3],
                    smA + a_off[mi] + kadd);
        uint32_t bfr[8][2];
        #pragma unroll
        for (int pi = 0; pi < 4; pi++) {
            uint32_t r0, r1, r2, r3;
            ldsm_x4(r0, r1, r2, r3, smBH + b_off[pi] + kadd);
            bfr[pi * 2][0] = r0; bfr[pi * 2][1] = r1;
            bfr[pi * 2 + 1][0] = r2; bfr[pi * 2 + 1][1] = r3;
        }
        #pragma unroll
        for (int ni = 0; ni < 8; ni++) {
            mma16816(acc[0][ni], afr[0], bfr[ni]);
            mma16816(acc[1][ni], afr[1], bfr[ni]);
        }
        #pragma unroll
        for (int pi = 0; pi < 4; pi++) {
            uint32_t r0, r1, r2, r3;
            ldsm_x4(r0, r1, r2, r3, smBL + b_off[pi] + kadd);
            bfr[pi * 2][0] = r0; bfr[pi * 2][1] = r1;
            bfr[pi * 2 + 1][0] = r2; bfr[pi * 2 + 1][1] = r3;
        }
        #pragma unroll
        for (int ni = 0; ni < 8; ni++) {
            mma16816(acc[0][ni], afr[0], bfr[ni]);
            mma16816(acc[1][ni], afr[1], bfr[ni]);
        }
    }

    // ---- reload A tile with A_lo ----
    __syncthreads();
    #pragma unroll
    for (int i = tid; i < 128 * CR; i += 256) {
        int r = i / CR, c16 = i % CR;
        int doff = r * PITCH + c16 * 16;
        uint4 vl = make_uint4(0, 0, 0, 0);
        if (row0 + r < M) {
            if (NORM) {
                float h[8];
                z_to_h8(g_zh + (size_t)(row0 + r) * HID + c16 * 8, s_sc, s_sh, c16 * 8, h);
                __nv_bfloat162* o = (__nv_bfloat162*)&vl;
                #pragma unroll
                for (int j = 0; j < 4; j++) {
                    float h0 = h[2 * j], h1 = h[2 * j + 1];
                    __nv_bfloat16 hi0 = __float2bfloat16(h0);
                    __nv_bfloat16 hi1 = __float2bfloat16(h1);
                    o[j] = __nv_bfloat162(__float2bfloat16(h0 - __bfloat162float(hi0)),
                                          __float2bfloat16(h1 - __bfloat162float(hi1)));
                }
            } else {
                vl = a_lo[(size_t)(row0 + r) * 16 + c16];
            }
        }
        *(uint4*)(smem + SM_A + doff) = vl;
    }
    __syncthreads();

    // ---- phase 2: A_lo x B_hi ----
    #pragma unroll
    for (int k16 = 0; k16 < KSTEPS; k16++) {
        uint32_t kadd = k16 * 32;
        uint32_t afr[2][4];
        #pragma unroll
        for (int mi = 0; mi < 2; mi++)
            ldsm_x4(afr[mi][0], afr[mi][1], afr[mi][2], afr[mi][3],
                    smA + a_off[mi] + kadd);
        uint32_t bfr[8][2];
        #pragma unroll
        for (int pi = 0; pi < 4; pi++) {
            uint32_t r0, r1, r2, r3;
            ldsm_x4(r0, r1, r2, r3, smBH + b_off[pi] + kadd);
            bfr[pi * 2][0] = r0; bfr[pi * 2][1] = r1;
            bfr[pi * 2 + 1][0] = r2; bfr[pi * 2 + 1][1] = r3;
        }
        #pragma unroll
        for (int ni = 0; ni < 8; ni++) {
            mma16816(acc[0][ni], afr[0], bfr[ni]);
            mma16816(acc[1][ni], afr[1], bfr[ni]);
        }
    }

    // ---- epilogue: half 0 -> g_yh (fp16), half 1 -> g_zh (fp16 + bias) ----
    __half* O = half ? g_zh : g_yh;
    #pragma unroll
    for (int mi = 0; mi < 2; mi++) {
        int r0 = row0 + wm * 32 + mi * 16 + (lane >> 2);
        #pragma unroll
        for (int ni = 0; ni < 8; ni++) {
            int c = wn * 64 + ni * 8 + (lane & 3) * 2;
            float bx = 0.f, by = 0.f;
            if (half) { bx = bias[c]; by = bias[c + 1]; }
            if (r0 < M) {
                __half2 v = __floats2half2_rn(acc[mi][ni][0] + bx, acc[mi][ni][1] + by);
                *(__half2*)&O[(size_t)r0 * HID + c] = v;
            }
            if (r0 + 8 < M) {
                __half2 v = __floats2half2_rn(acc[mi][ni][2] + bx, acc[mi][ni][3] + by);
                *(__half2*)&O[(size_t)(r0 + 8) * HID + c] = v;
            }
        }
    }
}

// ---------------- gather-mean + fused BN stats ------------------------------
__global__ void aggregate_kernel(int N, int layer) {
    __shared__ float sh_s[8][132];
    __shared__ float sh_q[8][132];
    int wid = threadIdx.x >> 5;
    int lane = threadIdx.x & 31;
    int d = blockIdx.x * 8 + wid;

    float4 z = make_float4(0.f, 0.f, 0.f, 0.f);
    if (d < N) {
        int s0 = g_row_start[d];
        int s1 = g_row_start[d + 1];
        int deg = s1 - s0;
        float inv = 1.0f / (float)(deg > 1 ? deg : 1);
        const uint2* Y = (const uint2*)g_yh;

        float4 acc = make_float4(0.f, 0.f, 0.f, 0.f);
        int j = s0;
        for (; j + 7 < s1; j += 8) {
            uint2 u[8];
            #pragma unroll
            for (int q = 0; q < 8; q++)
                u[q] = Y[(size_t)g_esrc[j + q] * 32 + lane];
            #pragma unroll
            for (int q = 0; q < 8; q++) {
                float2 f0 = __half22float2(*(__half2*)&u[q].x);
                float2 f1 = __half22float2(*(__half2*)&u[q].y);
                acc.x += f0.x; acc.y += f0.y; acc.z += f1.x; acc.w += f1.y;
            }
        }
        for (; j + 3 < s1; j += 4) {
            uint2 u[4];
            #pragma unroll
            for (int q = 0; q < 4; q++)
                u[q] = Y[(size_t)g_esrc[j + q] * 32 + lane];
            #pragma unroll
            for (int q = 0; q < 4; q++) {
                float2 f0 = __half22float2(*(__half2*)&u[q].x);
                float2 f1 = __half22float2(*(__half2*)&u[q].y);
                acc.x += f0.x; acc.y += f0.y; acc.z += f1.x; acc.w += f1.y;
            }
        }
        for (; j < s1; j++) {
            uint2 ua = Y[(size_t)g_esrc[j] * 32 + lane];
            float2 a0 = __half22float2(*(__half2*)&ua.x), a1 = __half22float2(*(__half2*)&ua.y);
            acc.x += a0.x; acc.y += a0.y; acc.z += a1.x; acc.w += a1.y;
        }

        uint2 uz = ((const uint2*)g_zh)[(size_t)d * 32 + lane];
        float2 z01 = __half22float2(*(__half2*)&uz.x);
        float2 z23 = __half22float2(*(__half2*)&uz.y);
        z.x = fmaf(acc.x, inv, z01.x);
        z.y = fmaf(acc.y, inv, z01.y);
        z.z = fmaf(acc.z, inv, z23.x);
        z.w = fmaf(acc.w, inv, z23.y);
        uint2 uo;
        *(__half2*)&uo.x = __floats2half2_rn(z.x, z.y);
        *(__half2*)&uo.y = __floats2half2_rn(z.z, z.w);
        ((uint2*)g_zh)[(size_t)d * 32 + lane] = uo;
    }

    // fused BN stats
    float4 q = make_float4(z.x * z.x, z.y * z.y, z.z * z.z, z.w * z.w);
    *(float4*)&sh_s[wid][4 * lane] = z;
    *(float4*)&sh_q[wid][4 * lane] = q;
    __syncthreads();
    int t = threadIdx.x;
    if (t < HID) {
        float s = 0.f;
        #pragma unroll
        for (int w = 0; w < 8; w++) s += sh_s[w][t];
        atomicAdd(&g_statp[layer][t][0], s);
    } else {
        int c = t - HID;
        float s = 0.f;
        #pragma unroll
        for (int w = 0; w < 8; w++) s += sh_q[w][c];
        atomicAdd(&g_statp[layer][HID + c][0], s);
    }
}

// ---------------- fused norm + global mean pool + MLP head ------------------
__global__ void pool_head_kernel(const float* __restrict__ gamma,
                                 const float* __restrict__ beta,
                                 const float* __restrict__ Wh1,
                                 const float* __restrict__ bh1,
                                 const float* __restrict__ Wh2,
                                 const float* __restrict__ bh2,
                                 float* __restrict__ out, int G, int N)
{
    __shared__ float s_sc[HID];
    __shared__ float s_sh[HID];
    __shared__ float pooled[HID];
    __shared__ float sred[2];
    int g = blockIdx.x;
    int t = threadIdx.x;   // 0..127
    if (g >= G) return;

    if (t < HID) {
        float inv_m = 1.0f / (float)N;
        float mu = g_statp[2][t][0] * inv_m;
        float var = fmaxf(g_statp[2][HID + t][0] * inv_m - mu * mu, 0.f);
        float sc = gamma[t] * rsqrtf(var + EPS);
        s_sc[t] = sc;
        s_sh[t] = beta[t] - mu * sc;
    }
    __syncthreads();

    int r0 = g_gstart[g];
    int r1 = g_gstart[g + 1];
    float sc = s_sc[t], sh = s_sh[t];
    float s = 0.f;
    for (int r = r0; r < r1; r++) {
        float z = __half2float(g_zh[(size_t)r * HID + t]);
        s += fmaxf(fmaf(z, sc, sh), 0.f);
    }
    int cnt = r1 - r0;
    pooled[t] = s / (float)(cnt > 1 ? cnt : 1);
    __syncthreads();

    if (t < HIDH) {
        float acc = bh1[t];
        #pragma unroll 8
        for (int k = 0; k < HID; k++)
            acc = fmaf(pooled[k], Wh1[k * HIDH + t], acc);
        float v = fmaxf(acc, 0.f) * Wh2[t];
        #pragma unroll
        for (int off = 16; off; off >>= 1)
            v += __shfl_down_sync(0xffffffff, v, off);
        if ((t & 31) == 0) sred[t >> 5] = v;
    }
    __syncthreads();
    if (t == 0) out[g] = sred[0] + sred[1] + bh2[0];
}

// ---------------- launch ----------------
extern "C" void kernel_launch(void* const* d_in, const int* in_sizes, int n_in,
                              void* d_out, int out_size) {
    const float* x     = (const float*)d_in[0];
    const void*  ei    = d_in[1];
    const void*  batch = d_in[2];

    const float* W_n0 = (const float*)d_in[3];
    const float* b0   = (const float*)d_in[4];
    const float* W_r0 = (const float*)d_in[5];
    const float* g0   = (const float*)d_in[6];
    const float* be0  = (const float*)d_in[7];

    const float* W_n1 = (const float*)d_in[8];
    const float* b1   = (const float*)d_in[9];
    const float* W_r1 = (const float*)d_in[10];
    const float* g1   = (const float*)d_in[11];
    const float* be1  = (const float*)d_in[12];

    const float* W_n2 = (const float*)d_in[13];
    const float* b2   = (const float*)d_in[14];
    const float* W_r2 = (const float*)d_in[15];
    const float* g2   = (const float*)d_in[16];
    const float* be2  = (const float*)d_in[17];

    const float* Wh1 = (const float*)d_in[18];
    const float* bh1 = (const float*)d_in[19];
    const float* Wh2 = (const float*)d_in[20];
    const float* bh2 = (const float*)d_in[21];

    float* out = (float*)d_out;

    const int N = in_sizes[2];
    const int E = in_sizes[1] / 2;
    const int G = out_size;
    const int IN_CH = in_sizes[0] / N;

    cudaFuncSetAttribute((const void*)gemm_mma_kernel<5, false>,
                         cudaFuncAttributeMaxDynamicSharedMemorySize, SM_TOTAL);
    cudaFuncSetAttribute((const void*)gemm_mma_kernel<8, false>,
                         cudaFuncAttributeMaxDynamicSharedMemorySize, SM_TOTAL);
    cudaFuncSetAttribute((const void*)gemm_mma_kernel<8, true>,
                         cudaFuncAttributeMaxDynamicSharedMemorySize, SM_TOTAL);

    // ---- prep: flag/zero, detect dtype, CSR, segments ----
    prep0_kernel<<<(N + 255) / 256, 256>>>(N);
    detect_kernel<<<8, 256>>>(ei, in_sizes[1]);
    int nscan = (N + SCAN_B - 1) / SCAN_B;
    count_edges_kernel<<<(E + 255) / 256, 256>>>(ei, E);
    scan1_kernel<<<nscan, SCAN_B>>>(N);
    scan2_kernel<<<1, 32>>>(nscan);
    scan3_kernel<<<(N + 255) / 256, 256>>>(N, E);
    fill_edges_kernel<<<(E + 255) / 256, 256>>>(ei, E);
    gstart_kernel<<<(N + 256) / 256, 256>>>(batch, N, G);

    // ---- bf16 split preprocessing ----
    int ksteps0 = (IN_CH + 15) / 16;   // 5 for IN_CH=78
    int KW = (ksteps0 <= 5) ? 80 : KPAD;
    convert_x_kernel<<<(N * KW + 255) / 256, 256>>>(x, N, IN_CH, KW);
    {
        dim3 wgrid((256 * KPAD + 255) / 256, 3);
        prep_weights_kernel<<<wgrid, 256>>>(W_n0, W_r0, W_n1, W_r1, W_n2, W_r2, IN_CH);
    }

    dim3 gemm_grid((N + 127) / 128, 2);
    int agg_blocks = (N + 7) / 8;

    const float* bb[3] = {b0, b1, b2};
    const float* gg[3] = {g0, g1, g2};
    const float* be[3] = {be0, be1, be2};

    for (int l = 0; l < 3; l++) {
        const uint4* ahi = nullptr;
        const uint4* alo = nullptr;
        const uint4* bhi;
        const uint4* blo;
        void* p;
        if (l == 0) {
            cudaGetSymbolAddress(&p, g_ax_hi); ahi = (const uint4*)p;
            cudaGetSymbolAddress(&p, g_ax_lo); alo = (const uint4*)p;
        }
        cudaGetSymbolAddress(&p, g_bw_hi); bhi = (const uint4*)p + (size_t)l * (256 * KPAD / 8);
        cudaGetSymbolAddress(&p, g_bw_lo); blo = (const uint4*)p + (size_t)l * (256 * KPAD / 8);

        if (l == 0) {
            if (ksteps0 <= 5)
                gemm_mma_kernel<5, false><<<gemm_grid, 256, SM_TOTAL>>>(
                    ahi, alo, bhi, blo, bb[l], nullptr, nullptr, 0, N);
            else
                gemm_mma_kernel<8, false><<<gemm_grid, 256, SM_TOTAL>>>(
                    ahi, alo, bhi, blo, bb[l], nullptr, nullptr, 0, N);
        } else {
            gemm_mma_kernel<8, true><<<gemm_grid, 256, SM_TOTAL>>>(
                nullptr, nullptr, bhi, blo, bb[l], gg[l - 1], be[l - 1], l - 1, N);
        }
        aggregate_kernel<<<agg_blocks, 256>>>(N, l);
    }

    pool_head_kernel<<<G, HID>>>(gg[2], be[2], Wh1, bh1, Wh2, bh2, out, G, N);
}

// round 17
// speedup vs baseline: 1.2152x; 1.0163x over previous
#include <cuda_runtime.h>
#include <cuda_bf16.h>
#include <cuda_fp16.h>
#include <cstdint>

// ---------------- problem constants ----------------
#define N_NODES_MAX 50000
#define N_EDGES_MAX 800000
#define N_GRAPHS_MAX 1000
#define HID 128
#define HIDH 64
#define KPAD 128
#define EPS 1e-5f
#define SCAN_B 1024
#define MAX_BLOCKS ((N_NODES_MAX + SCAN_B - 1) / SCAN_B)
#define PER_HALF 152                     // GB300: 152 SMs, 2 CTAs/SM, 2 halves

// ---------------- scratch (device globals, allocation-free) ----------------
__device__ __align__(16) __half g_yh[N_NODES_MAX * HID];    // h @ W_n (fp16)
__device__ __align__(16) __half g_zh[N_NODES_MAX * HID];    // h @ W_r + b + agg (fp16)
__device__ __align__(16) __nv_bfloat16 g_ax_hi[N_NODES_MAX * KPAD];  // layer-0 A split
__device__ __align__(16) __nv_bfloat16 g_ax_lo[N_NODES_MAX * KPAD];
__device__ __align__(16) __nv_bfloat16 g_bw_hi[3][256 * KPAD];   // [Wn|Wr]^T hi, [n][k]
__device__ __align__(16) __nv_bfloat16 g_bw_lo[3][256 * KPAD];
__device__ int   g_is64;
__device__ int   g_indeg[N_NODES_MAX];
__device__ int   g_rowexcl[N_NODES_MAX];
__device__ int   g_bsum[MAX_BLOCKS];
__device__ int   g_bsumex[MAX_BLOCKS];
__device__ int   g_row_start[N_NODES_MAX + 1];
__device__ int   g_epos[N_NODES_MAX];
__device__ int   g_esrc[N_EDGES_MAX];
__device__ int   g_gstart[N_GRAPHS_MAX + 1];
__device__ float g_statp[3][2 * HID][32];    // padded: one 128B line per stat

// ---------------- index-width handling ----------------
__device__ __forceinline__ int ld_idx(const void* p, long long i, int is64) {
    if (is64) return (int)((const long long*)p)[i];
    return ((const int*)p)[i];
}

// ---------------- combined prep: flag init + zero indeg + zero stats -------
__global__ void prep0_kernel(int N) {
    int i = blockIdx.x * blockDim.x + threadIdx.x;
    if (i == 0) g_is64 = 1;
    if (i < N) g_indeg[i] = 0;
    if (i < 3 * 2 * HID) g_statp[i / (2 * HID)][i % (2 * HID)][0] = 0.f;
}

__global__ void detect_kernel(const void* ei, int n_i32) {
    int i = blockIdx.x * blockDim.x + threadIdx.x;
    int idx = 2 * i + 1;
    if (idx < n_i32 && ((const int*)ei)[idx] != 0) g_is64 = 0;
}

// ---------------- CSR build ----------------
__global__ void count_edges_kernel(const void* __restrict__ ei, int E) {
    int e = blockIdx.x * blockDim.x + threadIdx.x;
    if (e >= E) return;
    atomicAdd(&g_indeg[ld_idx(ei, (long long)E + e, g_is64)], 1);
}

__global__ void scan1_kernel(int N) {
    __shared__ int sh[SCAN_B];
    int i = blockIdx.x * SCAN_B + threadIdx.x;
    int v = (i < N) ? g_indeg[i] : 0;
    sh[threadIdx.x] = v;
    __syncthreads();
    #pragma unroll
    for (int off = 1; off < SCAN_B; off <<= 1) {
        int t = 0;
        if (threadIdx.x >= off) t = sh[threadIdx.x - off];
        __syncthreads();
        sh[threadIdx.x] += t;
        __syncthreads();
    }
    if (i < N) g_rowexcl[i] = sh[threadIdx.x] - v;
    if (threadIdx.x == SCAN_B - 1) g_bsum[blockIdx.x] = sh[SCAN_B - 1];
}

__global__ void scan2_kernel(int nblocks) {
    if (threadIdx.x == 0) {
        int run = 0;
        for (int b = 0; b < nblocks; b++) { int t = g_bsum[b]; g_bsumex[b] = run; run += t; }
    }
}

__global__ void scan3_kernel(int N, int E) {
    int i = blockIdx.x * blockDim.x + threadIdx.x;
    if (i < N) {
        int v = g_rowexcl[i] + g_bsumex[i >> 10];
        g_row_start[i] = v;
        g_epos[i] = v;
    }
    if (i == 0) g_row_start[N] = E;
}

__global__ void fill_edges_kernel(const void* __restrict__ ei, int E) {
    int e = blockIdx.x * blockDim.x + threadIdx.x;
    if (e >= E) return;
    int is64 = g_is64;
    int s = ld_idx(ei, e, is64);
    int d = ld_idx(ei, (long long)E + e, is64);
    g_esrc[atomicAdd(&g_epos[d], 1)] = s;
}

__global__ void gstart_kernel(const void* __restrict__ batch, int N, int G) {
    int i = blockIdx.x * blockDim.x + threadIdx.x;
    if (i > N) return;
    int is64 = g_is64;
    int cur  = (i == N) ? G : ld_idx(batch, i, is64);
    int prev = (i == 0) ? -1 : ld_idx(batch, i - 1, is64);
    for (int g = prev + 1; g <= cur && g <= G; g++) g_gstart[g] = i;
}

// ---------------- bf16 split conversions ----------------
// writes only the first KW columns (row stride stays KPAD)
__global__ void convert_x_kernel(const float* __restrict__ x, int N, int IN_CH, int KW) {
    int idx = blockIdx.x * blockDim.x + threadIdx.x;
    if (idx >= N * KW) return;
    int r = idx / KW, k = idx % KW;
    float v = (k < IN_CH) ? x[(size_t)r * IN_CH + k] : 0.f;
    __nv_bfloat16 hi = __float2bfloat16(v);
    size_t o = (size_t)r * KPAD + k;
    g_ax_hi[o] = hi;
    g_ax_lo[o] = __float2bfloat16(v - __bfloat162float(hi));
}

// one launch for all 3 layers: blockIdx.y = layer
__global__ void prep_weights_kernel(const float* __restrict__ Wn0, const float* __restrict__ Wr0,
                                    const float* __restrict__ Wn1, const float* __restrict__ Wr1,
                                    const float* __restrict__ Wn2, const float* __restrict__ Wr2,
                                    int IN_CH) {
    int idx = blockIdx.x * blockDim.x + threadIdx.x;
    if (idx >= 256 * KPAD) return;
    int layer = blockIdx.y;
    const float* Wn = (layer == 0) ? Wn0 : (layer == 1) ? Wn1 : Wn2;
    const float* Wr = (layer == 0) ? Wr0 : (layer == 1) ? Wr1 : Wr2;
    int K_real = (layer == 0) ? IN_CH : HID;
    int n = idx >> 7, k = idx & 127;
    float v = 0.f;
    if (k < K_real) v = (n < HID) ? Wn[(size_t)k * HID + n] : Wr[(size_t)k * HID + (n - HID)];
    __nv_bfloat16 hi = __float2bfloat16(v);
    g_bw_hi[layer][idx] = hi;
    g_bw_lo[layer][idx] = __float2bfloat16(v - __bfloat162float(hi));
}

// ---------------- persistent mma.sync dual GEMM ----------------------------
// Template: KSTEPS = k16 steps (5 for layer 0, 8 for layers 1/2);
//           NORM   = A comes from g_zh with fused BN+ReLU+bf16-split
// grid = 2*PER_HALF; half = blockIdx.x & 1; CTA loops m-tiles with stride PER_HALF.
// B hi/lo tiles and BN scale/shift are loaded ONCE per CTA.
#define PITCH 272
#define A_TILE (128 * PITCH)            // 34816
#define SM_A    0
#define SM_B_HI A_TILE
#define SM_B_LO (2 * A_TILE)
#define SM_TOTAL (3 * A_TILE)           // 104448

__device__ __forceinline__ uint32_t smem_u32(const void* p) {
    uint32_t a;
    asm("{ .reg .u64 t; cvta.to.shared.u64 t, %1; cvt.u32.u64 %0, t; }" : "=r"(a) : "l"(p));
    return a;
}

__device__ __forceinline__ void ldsm_x4(uint32_t& r0, uint32_t& r1, uint32_t& r2, uint32_t& r3,
                                        uint32_t addr) {
    asm volatile("ldmatrix.sync.aligned.m8n8.x4.shared.b16 {%0,%1,%2,%3}, [%4];"
                 : "=r"(r0), "=r"(r1), "=r"(r2), "=r"(r3) : "r"(addr));
}

__device__ __forceinline__ void mma16816(float* c, const uint32_t* a, const uint32_t* b) {
    asm volatile(
        "mma.sync.aligned.m16n8k16.row.col.f32.bf16.bf16.f32 "
        "{%0,%1,%2,%3}, {%4,%5,%6,%7}, {%8,%9}, {%0,%1,%2,%3};"
        : "+f"(c[0]), "+f"(c[1]), "+f"(c[2]), "+f"(c[3])
        : "r"(a[0]), "r"(a[1]), "r"(a[2]), "r"(a[3]), "r"(b[0]), "r"(b[1]));
}

// convert one 8-element chunk of z-row into normed/relu'd fp32
__device__ __forceinline__ void z_to_h8(const __half* zrow, const float* s_sc,
                                        const float* s_sh, int cbase, float* h) {
    uint4 vz = *(const uint4*)zrow;
    const __half2* hp = (const __half2*)&vz;
    #pragma unroll
    for (int j = 0; j < 4; j++) {
        float2 f = __half22float2(hp[j]);
        h[2 * j]     = f.x;
        h[2 * j + 1] = f.y;
    }
    #pragma unroll
    for (int j = 0; j < 8; j++)
        h[j] = fmaxf(fmaf(h[j], s_sc[cbase + j], s_sh[cbase + j]), 0.f);
}

template <int KSTEPS, bool NORM>
__global__ __launch_bounds__(256, 2)
void gemm_mma_kernel(const uint4* __restrict__ a_hi, const uint4* __restrict__ a_lo,
                     const uint4* __restrict__ b_hi, const uint4* __restrict__ b_lo,
                     const float* __restrict__ bias,
                     const float* __restrict__ pgamma, const float* __restrict__ pbeta,
                     int prev_layer, int M)
{
    constexpr int CR = 2 * KSTEPS;      // uint4 column-chunks used per row
    extern __shared__ char smem[];
    __shared__ float s_sc[HID];
    __shared__ float s_sh[HID];
    uint32_t sbase = smem_u32(smem);

    int tid = threadIdx.x;
    int lane = tid & 31;
    int wid = tid >> 5;
    int wm = wid & 3;
    int wn = wid >> 2;
    int half = blockIdx.x & 1;
    int cih  = blockIdx.x >> 1;          // CTA index within half: 0..PER_HALF-1
    int brow0 = half * 128;
    int NB = (M + 127) >> 7;

    if (NORM) {
        if (tid < HID) {
            float inv_m = 1.0f / (float)M;
            float mu = g_statp[prev_layer][tid][0] * inv_m;
            float var = fmaxf(g_statp[prev_layer][HID + tid][0] * inv_m - mu * mu, 0.f);
            float sc = pgamma[tid] * rsqrtf(var + EPS);
            s_sc[tid] = sc;
            s_sh[tid] = pbeta[tid] - mu * sc;
        }
    }

    // ---- load B tiles once per CTA ----
    #pragma unroll
    for (int i = tid; i < 128 * CR; i += 256) {
        int r = i / CR, c16 = i % CR;
        int doff = r * PITCH + c16 * 16;
        *(uint4*)(smem + SM_B_HI + doff) = b_hi[(size_t)(brow0 + r) * 16 + c16];
        *(uint4*)(smem + SM_B_LO + doff) = b_lo[(size_t)(brow0 + r) * 16 + c16];
    }

    uint32_t a_off[2];
    #pragma unroll
    for (int mi = 0; mi < 2; mi++)
        a_off[mi] = (uint32_t)((wm * 32 + mi * 16 + (lane & 15)) * PITCH + (lane >> 4) * 16);
    uint32_t b_off[4];
    {
        int grp = lane >> 3, rin = lane & 7;
        int radd = (grp >= 2) ? 8 : 0;
        int koff = (grp & 1) * 16;
        #pragma unroll
        for (int pi = 0; pi < 4; pi++)
            b_off[pi] = (uint32_t)((wn * 64 + pi * 16 + radd + rin) * PITCH + koff);
    }

    uint32_t smA  = sbase + SM_A;
    uint32_t smBH = sbase + SM_B_HI;
    uint32_t smBL = sbase + SM_B_LO;
    __half* O = half ? g_zh : g_yh;

    for (int mt = cih; mt < NB; mt += PER_HALF) {
        int row0 = mt << 7;

        // protect A smem from previous tile's phase-2 reads; first iter orders B/s_sc too
        __syncthreads();

        // ---- load A_hi ----
        #pragma unroll
        for (int i = tid; i < 128 * CR; i += 256) {
            int r = i / CR, c16 = i % CR;
            int doff = r * PITCH + c16 * 16;
            uint4 vh = make_uint4(0, 0, 0, 0);
            if (row0 + r < M) {
                if (NORM) {
                    float h[8];
                    z_to_h8(g_zh + (size_t)(row0 + r) * HID + c16 * 8, s_sc, s_sh, c16 * 8, h);
                    __nv_bfloat162* o = (__nv_bfloat162*)&vh;
                    #pragma unroll
                    for (int j = 0; j < 4; j++)
                        o[j] = __nv_bfloat162(__float2bfloat16(h[2 * j]),
                                              __float2bfloat16(h[2 * j + 1]));
                } else {
                    vh = a_hi[(size_t)(row0 + r) * 16 + c16];
                }
            }
            *(uint4*)(smem + SM_A + doff) = vh;
        }
        __syncthreads();

        float acc[2][8][4];
        #pragma unroll
        for (int mi = 0; mi < 2; mi++)
            #pragma unroll
            for (int ni = 0; ni < 8; ni++)
                #pragma unroll
                for (int q = 0; q < 4; q++) acc[mi][ni][q] = 0.f;

        // ---- phase 1: A_hi x B_hi and A_hi x B_lo (shared A fragments) ----
        #pragma unroll
        for (int k16 = 0; k16 < KSTEPS; k16++) {
            uint32_t kadd = k16 * 32;
            uint32_t afr[2][4];
            #pragma unroll
            for (int mi = 0; mi < 2; mi++)
                ldsm_x4(afr[mi][0], afr[mi][1], afr[mi][2], afr[mi][3],
                        smA + a_off[mi] + kadd);
            uint32_t bfr[8][2];
            #pragma unroll
            for (int pi = 0; pi < 4; pi++) {
                uint32_t r0, r1, r2, r3;
                ldsm_x4(r0, r1, r2, r3, smBH + b_off[pi] + kadd);
                bfr[pi * 2][0] = r0; bfr[pi * 2][1] = r1;
                bfr[pi * 2 + 1][0] = r2; bfr[pi * 2 + 1][1] = r3;
            }
            #pragma unroll
            for (int ni = 0; ni < 8; ni++) {
                mma16816(acc[0][ni], afr[0], bfr[ni]);
                mma16816(acc[1][ni], afr[1], bfr[ni]);
            }
            #pragma unroll
            for (int pi = 0; pi < 4; pi++) {
                uint32_t r0, r1, r2, r3;
                ldsm_x4(r0, r1, r2, r3, smBL + b_off[pi] + kadd);
                bfr[pi * 2][0] = r0; bfr[pi * 2][1] = r1;
                bfr[pi * 2 + 1][0] = r2; bfr[pi * 2 + 1][1] = r3;
            }
            #pragma unroll
            for (int ni = 0; ni < 8; ni++) {
                mma16816(acc[0][ni], afr[0], bfr[ni]);
                mma16816(acc[1][ni], afr[1], bfr[ni]);
            }
        }

        // ---- reload A tile with A_lo ----
        __syncthreads();
        #pragma unroll
        for (int i = tid; i < 128 * CR; i += 256) {
            int r = i / CR, c16 = i % CR;
            int doff = r * PITCH + c16 * 16;
            uint4 vl = make_uint4(0, 0, 0, 0);
            if (row0 + r < M) {
                if (NORM) {
                    float h[8];
                    z_to_h8(g_zh + (size_t)(row0 + r) * HID + c16 * 8, s_sc, s_sh, c16 * 8, h);
                    __nv_bfloat162* o = (__nv_bfloat162*)&vl;
                    #pragma unroll
                    for (int j = 0; j < 4; j++) {
                        float h0 = h[2 * j], h1 = h[2 * j + 1];
                        __nv_bfloat16 hi0 = __float2bfloat16(h0);
                        __nv_bfloat16 hi1 = __float2bfloat16(h1);
                        o[j] = __nv_bfloat162(__float2bfloat16(h0 - __bfloat162float(hi0)),
                                              __float2bfloat16(h1 - __bfloat162float(hi1)));
                    }
                } else {
                    vl = a_lo[(size_t)(row0 + r) * 16 + c16];
                }
            }
            *(uint4*)(smem + SM_A + doff) = vl;
        }
        __syncthreads();

        // ---- phase 2: A_lo x B_hi ----
        #pragma unroll
        for (int k16 = 0; k16 < KSTEPS; k16++) {
            uint32_t kadd = k16 * 32;
            uint32_t afr[2][4];
            #pragma unroll
            for (int mi = 0; mi < 2; mi++)
                ldsm_x4(afr[mi][0], afr[mi][1], afr[mi][2], afr[mi][3],
                        smA + a_off[mi] + kadd);
            uint32_t bfr[8][2];
            #pragma unroll
            for (int pi = 0; pi < 4; pi++) {
                uint32_t r0, r1, r2, r3;
                ldsm_x4(r0, r1, r2, r3, smBH + b_off[pi] + kadd);
                bfr[pi * 2][0] = r0; bfr[pi * 2][1] = r1;
                bfr[pi * 2 + 1][0] = r2; bfr[pi * 2 + 1][1] = r3;
            }
            #pragma unroll
            for (int ni = 0; ni < 8; ni++) {
                mma16816(acc[0][ni], afr[0], bfr[ni]);
                mma16816(acc[1][ni], afr[1], bfr[ni]);
            }
        }

        // ---- epilogue (registers -> global; no smem) ----
        #pragma unroll
        for (int mi = 0; mi < 2; mi++) {
            int r0 = row0 + wm * 32 + mi * 16 + (lane >> 2);
            #pragma unroll
            for (int ni = 0; ni < 8; ni++) {
                int c = wn * 64 + ni * 8 + (lane & 3) * 2;
                float bx = 0.f, by = 0.f;
                if (half) { bx = bias[c]; by = bias[c + 1]; }
                if (r0 < M) {
                    __half2 v = __floats2half2_rn(acc[mi][ni][0] + bx, acc[mi][ni][1] + by);
                    *(__half2*)&O[(size_t)r0 * HID + c] = v;
                }
                if (r0 + 8 < M) {
                    __half2 v = __floats2half2_rn(acc[mi][ni][2] + bx, acc[mi][ni][3] + by);
                    *(__half2*)&O[(size_t)(r0 + 8) * HID + c] = v;
                }
            }
        }
    }
}

// ---------------- gather-mean + fused BN stats ------------------------------
__global__ void aggregate_kernel(int N, int layer) {
    __shared__ float sh_s[8][132];
    __shared__ float sh_q[8][132];
    int wid = threadIdx.x >> 5;
    int lane = threadIdx.x & 31;
    int d = blockIdx.x * 8 + wid;

    float4 z = make_float4(0.f, 0.f, 0.f, 0.f);
    if (d < N) {
        int s0 = g_row_start[d];
        int s1 = g_row_start[d + 1];
        int deg = s1 - s0;
        float inv = 1.0f / (float)(deg > 1 ? deg : 1);
        const uint2* Y = (const uint2*)g_yh;

        float4 acc = make_float4(0.f, 0.f, 0.f, 0.f);
        int j = s0;
        for (; j + 7 < s1; j += 8) {
            uint2 u[8];
            #pragma unroll
            for (int q = 0; q < 8; q++)
                u[q] = Y[(size_t)g_esrc[j + q] * 32 + lane];
            #pragma unroll
            for (int q = 0; q < 8; q++) {
                float2 f0 = __half22float2(*(__half2*)&u[q].x);
                float2 f1 = __half22float2(*(__half2*)&u[q].y);
                acc.x += f0.x; acc.y += f0.y; acc.z += f1.x; acc.w += f1.y;
            }
        }
        for (; j + 3 < s1; j += 4) {
            uint2 u[4];
            #pragma unroll
            for (int q = 0; q < 4; q++)
                u[q] = Y[(size_t)g_esrc[j + q] * 32 + lane];
            #pragma unroll
            for (int q = 0; q < 4; q++) {
                float2 f0 = __half22float2(*(__half2*)&u[q].x);
                float2 f1 = __half22float2(*(__half2*)&u[q].y);
                acc.x += f0.x; acc.y += f0.y; acc.z += f1.x; acc.w += f1.y;
            }
        }
        for (; j < s1; j++) {
            uint2 ua = Y[(size_t)g_esrc[j] * 32 + lane];
            float2 a0 = __half22float2(*(__half2*)&ua.x), a1 = __half22float2(*(__half2*)&ua.y);
            acc.x += a0.x; acc.y += a0.y; acc.z += a1.x; acc.w += a1.y;
        }

        uint2 uz = ((const uint2*)g_zh)[(size_t)d * 32 + lane];
        float2 z01 = __half22float2(*(__half2*)&uz.x);
        float2 z23 = __half22float2(*(__half2*)&uz.y);
        z.x = fmaf(acc.x, inv, z01.x);
        z.y = fmaf(acc.y, inv, z01.y);
        z.z = fmaf(acc.z, inv, z23.x);
        z.w = fmaf(acc.w, inv, z23.y);
        uint2 uo;
        *(__half2*)&uo.x = __floats2half2_rn(z.x, z.y);
        *(__half2*)&uo.y = __floats2half2_rn(z.z, z.w);
        ((uint2*)g_zh)[(size_t)d * 32 + lane] = uo;
    }

    // fused BN stats
    float4 q = make_float4(z.x * z.x, z.y * z.y, z.z * z.z, z.w * z.w);
    *(float4*)&sh_s[wid][4 * lane] = z;
    *(float4*)&sh_q[wid][4 * lane] = q;
    __syncthreads();
    int t = threadIdx.x;
    if (t < HID) {
        float s = 0.f;
        #pragma unroll
        for (int w = 0; w < 8; w++) s += sh_s[w][t];
        atomicAdd(&g_statp[layer][t][0], s);
    } else {
        int c = t - HID;
        float s = 0.f;
        #pragma unroll
        for (int w = 0; w < 8; w++) s += sh_q[w][c];
        atomicAdd(&g_statp[layer][HID + c][0], s);
    }
}

// ---------------- fused norm + global mean pool + MLP head ------------------
__global__ void pool_head_kernel(const float* __restrict__ gamma,
                                 const float* __restrict__ beta,
                                 const float* __restrict__ Wh1,
                                 const float* __restrict__ bh1,
                                 const float* __restrict__ Wh2,
                                 const float* __restrict__ bh2,
                                 float* __restrict__ out, int G, int N)
{
    __shared__ float s_sc[HID];
    __shared__ float s_sh[HID];
    __shared__ float pooled[HID];
    __shared__ float sred[2];
    int g = blockIdx.x;
    int t = threadIdx.x;   // 0..127
    if (g >= G) return;

    if (t < HID) {
        float inv_m = 1.0f / (float)N;
        float mu = g_statp[2][t][0] * inv_m;
        float var = fmaxf(g_statp[2][HID + t][0] * inv_m - mu * mu, 0.f);
        float sc = gamma[t] * rsqrtf(var + EPS);
        s_sc[t] = sc;
        s_sh[t] = beta[t] - mu * sc;
    }
    __syncthreads();

    int r0 = g_gstart[g];
    int r1 = g_gstart[g + 1];
    float sc = s_sc[t], sh = s_sh[t];
    float s = 0.f;
    for (int r = r0; r < r1; r++) {
        float z = __half2float(g_zh[(size_t)r * HID + t]);
        s += fmaxf(fmaf(z, sc, sh), 0.f);
    }
    int cnt = r1 - r0;
    pooled[t] = s / (float)(cnt > 1 ? cnt : 1);
    __syncthreads();

    if (t < HIDH) {
        float acc = bh1[t];
        #pragma unroll 8
        for (int k = 0; k < HID; k++)
            acc = fmaf(pooled[k], Wh1[k * HIDH + t], acc);
        float v = fmaxf(acc, 0.f) * Wh2[t];
        #pragma unroll
        for (int off = 16; off; off >>= 1)
            v += __shfl_down_sync(0xffffffff, v, off);
        if ((t & 31) == 0) sred[t >> 5] = v;
    }
    __syncthreads();
    if (t == 0) out[g] = sred[0] + sred[1] + bh2[0];
}

// ---------------- launch ----------------
extern "C" void kernel_launch(void* const* d_in, const int* in_sizes, int n_in,
                              void* d_out, int out_size) {
    const float* x     = (const float*)d_in[0];
    const void*  ei    = d_in[1];
    const void*  batch = d_in[2];

    const float* W_n0 = (const float*)d_in[3];
    const float* b0   = (const float*)d_in[4];
    const float* W_r0 = (const float*)d_in[5];
    const float* g0   = (const float*)d_in[6];
    const float* be0  = (const float*)d_in[7];

    const float* W_n1 = (const float*)d_in[8];
    const float* b1   = (const float*)d_in[9];
    const float* W_r1 = (const float*)d_in[10];
    const float* g1   = (const float*)d_in[11];
    const float* be1  = (const float*)d_in[12];

    const float* W_n2 = (const float*)d_in[13];
    const float* b2   = (const float*)d_in[14];
    const float* W_r2 = (const float*)d_in[15];
    const float* g2   = (const float*)d_in[16];
    const float* be2  = (const float*)d_in[17];

    const float* Wh1 = (const float*)d_in[18];
    const float* bh1 = (const float*)d_in[19];
    const float* Wh2 = (const float*)d_in[20];
    const float* bh2 = (const float*)d_in[21];

    float* out = (float*)d_out;

    const int N = in_sizes[2];
    const int E = in_sizes[1] / 2;
    const int G = out_size;
    const int IN_CH = in_sizes[0] / N;

    cudaFuncSetAttribute((const void*)gemm_mma_kernel<5, false>,
                         cudaFuncAttributeMaxDynamicSharedMemorySize, SM_TOTAL);
    cudaFuncSetAttribute((const void*)gemm_mma_kernel<8, false>,
                         cudaFuncAttributeMaxDynamicSharedMemorySize, SM_TOTAL);
    cudaFuncSetAttribute((const void*)gemm_mma_kernel<8, true>,
                         cudaFuncAttributeMaxDynamicSharedMemorySize, SM_TOTAL);

    // ---- prep: flag/zero, detect dtype, CSR, segments ----
    prep0_kernel<<<(N + 255) / 256, 256>>>(N);
    detect_kernel<<<8, 256>>>(ei, in_sizes[1]);
    int nscan = (N + SCAN_B - 1) / SCAN_B;
    count_edges_kernel<<<(E + 255) / 256, 256>>>(ei, E);
    scan1_kernel<<<nscan, SCAN_B>>>(N);
    scan2_kernel<<<1, 32>>>(nscan);
    scan3_kernel<<<(N + 255) / 256, 256>>>(N, E);
    fill_edges_kernel<<<(E + 255) / 256, 256>>>(ei, E);
    gstart_kernel<<<(N + 256) / 256, 256>>>(batch, N, G);

    // ---- bf16 split preprocessing ----
    int ksteps0 = (IN_CH + 15) / 16;   // 5 for IN_CH=78
    int KW = (ksteps0 <= 5) ? 80 : KPAD;
    convert_x_kernel<<<(N * KW + 255) / 256, 256>>>(x, N, IN_CH, KW);
    {
        dim3 wgrid((256 * KPAD + 255) / 256, 3);
        prep_weights_kernel<<<wgrid, 256>>>(W_n0, W_r0, W_n1, W_r1, W_n2, W_r2, IN_CH);
    }

    int gemm_grid = 2 * PER_HALF;
    int agg_blocks = (N + 7) / 8;

    const float* bb[3] = {b0, b1, b2};
    const float* gg[3] = {g0, g1, g2};
    const float* be[3] = {be0, be1, be2};

    for (int l = 0; l < 3; l++) {
        const uint4* ahi = nullptr;
        const uint4* alo = nullptr;
        const uint4* bhi;
        const uint4* blo;
        void* p;
        if (l == 0) {
            cudaGetSymbolAddress(&p, g_ax_hi); ahi = (const uint4*)p;
            cudaGetSymbolAddress(&p, g_ax_lo); alo = (const uint4*)p;
        }
        cudaGetSymbolAddress(&p, g_bw_hi); bhi = (const uint4*)p + (size_t)l * (256 * KPAD / 8);
        cudaGetSymbolAddress(&p, g_bw_lo); blo = (const uint4*)p + (size_t)l * (256 * KPAD / 8);

        if (l == 0) {
            if (ksteps0 <= 5)
                gemm_mma_kernel<5, false><<<gemm_grid, 256, SM_TOTAL>>>(
                    ahi, alo, bhi, blo, bb[l], nullptr, nullptr, 0, N);
            else
                gemm_mma_kernel<8, false><<<gemm_grid, 256, SM_TOTAL>>>(
                    ahi, alo, bhi, blo, bb[l], nullptr, nullptr, 0, N);
        } else {
            gemm_mma_kernel<8, true><<<gemm_grid, 256, SM_TOTAL>>>(
                nullptr, nullptr, bhi, blo, bb[l], gg[l - 1], be[l - 1], l - 1, N);
        }
        aggregate_kernel<<<agg_blocks, 256>>>(N, l);
    }

    pool_head_kernel<<<G, HID>>>(gg[2], be[2], Wh1, bh1, Wh2, bh2, out, G, N);
}